// round 6
// baseline (speedup 1.0000x reference)
#include <cuda_runtime.h>
#include <math.h>

// Problem constants
#define NB    256
#define TT    2048
#define CIN   18      // C*S = 9*2
#define H1C   32
#define H2C   64
#define ND    3
#define ED    64
#define TILE  128
#define NCODE 240

// Output packing (flattened, concatenated, float32):
// codes [B,T], out [B,64,T], perplexity [1], probs [240]
#define OFF_CODES 0L
#define OFF_OUT   ((long)NB * TT)                        // 524288
#define OFF_PERP  (OFF_OUT + (long)NB * ED * TT)         // 34078720
#define OFF_PROBS (OFF_PERP + 1)                         // 34078721

__device__ int g_counts[NCODE];

// Replicate jnp.linspace(-1, 1, L, float32): step = fl32(2/(L-1)), b_i = fl32(-1 + i*step)
__device__ __forceinline__ float lspf(int i, int L) {
    float step = 2.0f / (float)(L - 1);   // compile-time fp32 constant
    return -1.0f + (float)i * step;
}

// argmin vs linspace(-1,1,L) == count of midpoints strictly below x
// (feat==midpoint -> lower index, matching argmin first-min tie rule)
template <int L>
__device__ __forceinline__ int quant_idx(float feat) {
    int idx = 0;
    #pragma unroll
    for (int i = 0; i < L - 1; i++) {
        float m = 0.5f * (lspf(i, L) + lspf(i + 1, L));
        idx += (feat > m);
    }
    return idx;
}

struct Smem {
    float w1s[CIN * 3 * H1C];   // [cin*3+k][co]   (transposed for broadcast f4)
    float w2s[H1C * 3 * H2C];   // [ci*3+k][co]
    float w3s[ND * H2C];        // [d][co]
    float wps[ED * ND];         // [e][d]
    float b1s[H1C];
    float b2s[H2C];
    float b3s[4];
    float bps[ED];
    float h1s[H1C][TILE + 4];   // columns 0..129 = t0-1 .. t0+128
    int   hist[NCODE];
};

__global__ void zero_counts_kernel() {
    int i = threadIdx.x;
    if (i < NCODE) g_counts[i] = 0;
}

__global__ __launch_bounds__(128) void fsq_main_kernel(
    const float* __restrict__ x,
    const float* __restrict__ w1, const float* __restrict__ b1,
    const float* __restrict__ w2, const float* __restrict__ b2,
    const float* __restrict__ w3, const float* __restrict__ b3,
    const float* __restrict__ wp, const float* __restrict__ bp,
    float* __restrict__ out)
{
    extern __shared__ Smem smem[];
    Smem* S = smem;
    const int tid = threadIdx.x;
    const int blk = blockIdx.x;
    const int b   = blk / (TT / TILE);
    const int t0  = (blk % (TT / TILE)) * TILE;

    // ---- stage weights into SMEM (transpose conv weights to [rk][co]) ----
    for (int i = tid; i < CIN * 3 * H1C; i += 128) {
        int co = i % H1C, rk = i / H1C;            // rk = cin*3+k
        S->w1s[i] = w1[co * (CIN * 3) + rk];
    }
    for (int i = tid; i < H1C * 3 * H2C; i += 128) {
        int co = i % H2C, rk = i / H2C;            // rk = ci*3+k
        S->w2s[i] = w2[co * (H1C * 3) + rk];
    }
    for (int i = tid; i < ND * H2C; i += 128) S->w3s[i] = w3[i];
    for (int i = tid; i < ED * ND;  i += 128) S->wps[i] = wp[i];
    if (tid < H1C) S->b1s[tid] = b1[tid];
    if (tid < H2C) S->b2s[tid] = b2[tid];
    if (tid < ND)  S->b3s[tid] = b3[tid];
    if (tid < ED)  S->bps[tid] = bp[tid];
    for (int i = tid; i < NCODE; i += 128) S->hist[i] = 0;
    __syncthreads();

    // ---- conv1 (18 -> 32, k=3, pad=1) + ReLU into SMEM h1 tile with halo ----
    // cuDNN implicit-GEMM numerics: acc starts at 0, strict sequential FMA over
    // K in (cin, kw) order, bias added in epilogue. Zero-padding contributes
    // exact fma(0,w,acc)=acc, identical to reference's padded sum.
    const float* xb = x + (long)b * CIN * TT;
    for (int i = tid; i < TILE + 2; i += 128) {
        int tp = t0 + i - 1;                       // h1 position for this column
        if (tp >= 0 && tp < TT) {
            float acc1[H1C];
            #pragma unroll
            for (int c = 0; c < H1C; c++) acc1[c] = 0.0f;
            #pragma unroll 1
            for (int cin = 0; cin < CIN; cin++) {
                const float* xr = xb + cin * TT + tp;
                float a0 = (tp > 0)      ? __ldg(xr - 1) : 0.0f;
                float a1 =                 __ldg(xr);
                float a2 = (tp < TT - 1) ? __ldg(xr + 1) : 0.0f;
                const float4* u0 = (const float4*)&S->w1s[cin * 96];
                const float4* u1 = (const float4*)&S->w1s[cin * 96 + 32];
                const float4* u2 = (const float4*)&S->w1s[cin * 96 + 64];
                #pragma unroll
                for (int j = 0; j < 8; j++) {
                    float4 v0 = u0[j], v1 = u1[j], v2 = u2[j];
                    acc1[4*j+0] = fmaf(a0, v0.x, acc1[4*j+0]);
                    acc1[4*j+1] = fmaf(a0, v0.y, acc1[4*j+1]);
                    acc1[4*j+2] = fmaf(a0, v0.z, acc1[4*j+2]);
                    acc1[4*j+3] = fmaf(a0, v0.w, acc1[4*j+3]);
                    acc1[4*j+0] = fmaf(a1, v1.x, acc1[4*j+0]);
                    acc1[4*j+1] = fmaf(a1, v1.y, acc1[4*j+1]);
                    acc1[4*j+2] = fmaf(a1, v1.z, acc1[4*j+2]);
                    acc1[4*j+3] = fmaf(a1, v1.w, acc1[4*j+3]);
                    acc1[4*j+0] = fmaf(a2, v2.x, acc1[4*j+0]);
                    acc1[4*j+1] = fmaf(a2, v2.y, acc1[4*j+1]);
                    acc1[4*j+2] = fmaf(a2, v2.z, acc1[4*j+2]);
                    acc1[4*j+3] = fmaf(a2, v2.w, acc1[4*j+3]);
                }
            }
            #pragma unroll
            for (int c = 0; c < H1C; c++)
                S->h1s[c][i] = fmaxf(__fadd_rn(acc1[c], S->b1s[c]), 0.0f);
        } else {
            #pragma unroll
            for (int c = 0; c < H1C; c++) S->h1s[c][i] = 0.0f;   // global zero-pad
        }
    }
    __syncthreads();

    // ---- conv2 (32 -> 64, k=3, pad=1) + ReLU: same strict (ci, kw) FMA order ----
    const int t = t0 + tid;
    float acc[H2C];
    #pragma unroll
    for (int c = 0; c < H2C; c++) acc[c] = 0.0f;
    #pragma unroll 1
    for (int ci = 0; ci < H1C; ci++) {
        float a0 = S->h1s[ci][tid];
        float a1 = S->h1s[ci][tid + 1];
        float a2 = S->h1s[ci][tid + 2];
        const float4* u0 = (const float4*)&S->w2s[ci * 192];
        const float4* u1 = (const float4*)&S->w2s[ci * 192 + 64];
        const float4* u2 = (const float4*)&S->w2s[ci * 192 + 128];
        #pragma unroll
        for (int j = 0; j < 16; j++) {
            float4 v0 = u0[j], v1 = u1[j], v2 = u2[j];
            acc[4*j+0] = fmaf(a0, v0.x, acc[4*j+0]);
            acc[4*j+1] = fmaf(a0, v0.y, acc[4*j+1]);
            acc[4*j+2] = fmaf(a0, v0.z, acc[4*j+2]);
            acc[4*j+3] = fmaf(a0, v0.w, acc[4*j+3]);
            acc[4*j+0] = fmaf(a1, v1.x, acc[4*j+0]);
            acc[4*j+1] = fmaf(a1, v1.y, acc[4*j+1]);
            acc[4*j+2] = fmaf(a1, v1.z, acc[4*j+2]);
            acc[4*j+3] = fmaf(a1, v1.w, acc[4*j+3]);
            acc[4*j+0] = fmaf(a2, v2.x, acc[4*j+0]);
            acc[4*j+1] = fmaf(a2, v2.y, acc[4*j+1]);
            acc[4*j+2] = fmaf(a2, v2.z, acc[4*j+2]);
            acc[4*j+3] = fmaf(a2, v2.w, acc[4*j+3]);
        }
    }
    #pragma unroll
    for (int c = 0; c < H2C; c++)
        acc[c] = fmaxf(__fadd_rn(acc[c], S->b2s[c]), 0.0f);

    // ---- conv3 (64 -> 3, k=1): sequential K FMA chain, bias epilogue; tanh ----
    int idx0, idx1, idx2;
    float qv0, qv1, qv2;
    {
        float s0 = 0.0f, s1 = 0.0f, s2 = 0.0f;
        #pragma unroll
        for (int c = 0; c < H2C; c++) {
            s0 = fmaf(acc[c], S->w3s[0 * H2C + c], s0);
            s1 = fmaf(acc[c], S->w3s[1 * H2C + c], s1);
            s2 = fmaf(acc[c], S->w3s[2 * H2C + c], s2);
        }
        float f0 = tanhf(__fadd_rn(s0, S->b3s[0]));
        float f1 = tanhf(__fadd_rn(s1, S->b3s[1]));
        float f2 = tanhf(__fadd_rn(s2, S->b3s[2]));
        idx0 = quant_idx<8>(f0);
        idx1 = quant_idx<6>(f1);
        idx2 = quant_idx<5>(f2);
        // STE forward value: fl(f + fl(q - f)) — replicate reference exactly
        qv0 = __fadd_rn(f0, __fsub_rn(lspf(idx0, 8), f0));
        qv1 = __fadd_rn(f1, __fsub_rn(lspf(idx1, 6), f1));
        qv2 = __fadd_rn(f2, __fsub_rn(lspf(idx2, 5), f2));
    }
    int code = idx0 + idx1 * 8 + idx2 * 48;
    atomicAdd(&S->hist[code], 1);
    out[OFF_CODES + (long)b * TT + t] = (float)code;

    // ---- projection (3 -> 64, k=1): sequential K FMA from 0, bias epilogue ----
    {
        long ob = OFF_OUT + (long)b * ED * TT + t;
        #pragma unroll
        for (int e = 0; e < ED; e++) {
            float s = __fmul_rn(qv0, S->wps[e * 3 + 0]);
            s = fmaf(qv1, S->wps[e * 3 + 1], s);
            s = fmaf(qv2, S->wps[e * 3 + 2], s);
            out[ob + (long)e * TT] = __fadd_rn(s, S->bps[e]);
        }
    }

    __syncthreads();
    for (int i = tid; i < NCODE; i += 128) {
        int h = S->hist[i];
        if (h) atomicAdd(&g_counts[i], h);
    }
}

__global__ void finalize_kernel(float* __restrict__ out) {
    __shared__ float red[256];
    int tid = threadIdx.x;
    float term = 0.0f;
    if (tid < NCODE) {
        float c = (float)g_counts[tid];
        float p = c * (1.0f / (float)((long)NB * TT));
        out[OFF_PROBS + tid] = p;
        if (p > 0.0f) term = -p * logf(p);
    }
    red[tid] = term;
    __syncthreads();
    #pragma unroll
    for (int s = 128; s > 0; s >>= 1) {
        if (tid < s) red[tid] += red[tid + s];
        __syncthreads();
    }
    if (tid == 0) out[OFF_PERP] = fmaxf(expf(red[0]), 1.0f);
}

extern "C" void kernel_launch(void* const* d_in, const int* in_sizes, int n_in,
                              void* d_out, int out_size) {
    const float* x  = (const float*)d_in[0];
    const float* w1 = (const float*)d_in[1];
    const float* b1 = (const float*)d_in[2];
    const float* w2 = (const float*)d_in[3];
    const float* b2 = (const float*)d_in[4];
    const float* w3 = (const float*)d_in[5];
    const float* b3 = (const float*)d_in[6];
    const float* wp = (const float*)d_in[7];
    const float* bp = (const float*)d_in[8];
    float* out = (float*)d_out;

    cudaFuncSetAttribute(fsq_main_kernel,
                         cudaFuncAttributeMaxDynamicSharedMemorySize,
                         (int)sizeof(Smem));

    zero_counts_kernel<<<1, 256>>>();
    fsq_main_kernel<<<NB * (TT / TILE), 128, sizeof(Smem)>>>(
        x, w1, b1, w2, b2, w3, b3, wp, bp, out);
    finalize_kernel<<<1, 256>>>(out);
}

// round 7
// speedup vs baseline: 1.3711x; 1.3711x over previous
#include <cuda_runtime.h>
#include <math.h>

// Problem constants
#define NB    256
#define TT    2048
#define CIN   18      // C*S = 9*2
#define H1C   32
#define H2C   64
#define ND    3
#define ED    64
#define TILE  256     // t-positions per block; 2 per thread
#define NCODE 240

// Output packing (flattened, concatenated, float32):
// codes [B,T], out [B,64,T], perplexity [1], probs [240]
#define OFF_CODES 0L
#define OFF_OUT   ((long)NB * TT)                        // 524288
#define OFF_PERP  (OFF_OUT + (long)NB * ED * TT)         // 34078720
#define OFF_PROBS (OFF_PERP + 1)                         // 34078721

__device__ int g_counts[NCODE];

// Replicate jnp.linspace(-1, 1, L, float32)
__device__ __forceinline__ float lspf(int i, int L) {
    float step = 2.0f / (float)(L - 1);
    return -1.0f + (float)i * step;
}

// argmin vs linspace(-1,1,L) == count of midpoints strictly below x
template <int L>
__device__ __forceinline__ int quant_idx(float feat) {
    int idx = 0;
    #pragma unroll
    for (int i = 0; i < L - 1; i++) {
        float m = 0.5f * (lspf(i, L) + lspf(i + 1, L));
        idx += (feat > m);
    }
    return idx;
}

struct Smem {
    float w1s[CIN * 3 * H1C];   // [cin*3+k][co]
    float w2s[H1C * 3 * H2C];   // [ci*3+k][co]
    float w3s[ND * H2C];        // [d][co]
    float wps[ED * ND];         // [e][d]
    float b1s[H1C];
    float b2s[H2C];
    float b3s[4];
    float bps[ED];
    float h1s[H1C][TILE + 4];   // col j = position t0 + j - 1, j=0..257
    int   hist[NCODE];
};

__global__ __launch_bounds__(128) void fsq_main_kernel(
    const float* __restrict__ x,
    const float* __restrict__ w1, const float* __restrict__ b1,
    const float* __restrict__ w2, const float* __restrict__ b2,
    const float* __restrict__ w3, const float* __restrict__ b3,
    const float* __restrict__ wp, const float* __restrict__ bp,
    float* __restrict__ out)
{
    extern __shared__ Smem smem[];
    Smem* S = smem;
    const int tid = threadIdx.x;
    const int blk = blockIdx.x;
    const int b   = blk / (TT / TILE);
    const int t0  = (blk % (TT / TILE)) * TILE;

    // ---- stage weights into SMEM (transpose conv weights to [rk][co]) ----
    for (int i = tid; i < CIN * 3 * H1C; i += 128) {
        int co = i % H1C, rk = i / H1C;
        S->w1s[i] = w1[co * (CIN * 3) + rk];
    }
    for (int i = tid; i < H1C * 3 * H2C; i += 128) {
        int co = i % H2C, rk = i / H2C;
        S->w2s[i] = w2[co * (H1C * 3) + rk];
    }
    for (int i = tid; i < ND * H2C; i += 128) S->w3s[i] = w3[i];
    for (int i = tid; i < ED * ND;  i += 128) S->wps[i] = wp[i];
    if (tid < H1C) S->b1s[tid] = b1[tid];
    if (tid < H2C) S->b2s[tid] = b2[tid];
    if (tid < ND)  S->b3s[tid] = b3[tid];
    if (tid < ED)  S->bps[tid] = bp[tid];
    for (int i = tid; i < NCODE; i += 128) S->hist[i] = 0;
    __syncthreads();

    // ---- conv1 (18->32, k3, pad1) + ReLU into SMEM, two columns per thread
    // sharing weight loads. Numerics: acc from 0, strict (cin, kw) FMA chain
    // per output, bias in epilogue (identical to the passing R6 ordering).
    const float* xb = x + (long)b * CIN * TT;
    {
        const int iA = tid, iB = tid + 128;
        const int tpA = t0 + iA - 1, tpB = t0 + iB - 1;
        const bool vA = (tpA >= 0) && (tpA < TT);   // vB always in-range
        float accA[H1C], accB[H1C];
        #pragma unroll
        for (int c = 0; c < H1C; c++) { accA[c] = 0.0f; accB[c] = 0.0f; }
        #pragma unroll 1
        for (int cin = 0; cin < CIN; cin++) {
            const float* xr = xb + cin * TT;
            float a0A = (tpA > 0)      ? __ldg(xr + tpA - 1) : 0.0f;
            float a1A = vA             ? __ldg(xr + tpA)     : 0.0f;
            float a2A = (tpA < TT - 1) ? __ldg(xr + tpA + 1) : 0.0f;
            float a0B = __ldg(xr + tpB - 1);
            float a1B = __ldg(xr + tpB);
            float a2B = __ldg(xr + tpB + 1);
            const float4* u0 = (const float4*)&S->w1s[cin * 96];
            const float4* u1 = (const float4*)&S->w1s[cin * 96 + 32];
            const float4* u2 = (const float4*)&S->w1s[cin * 96 + 64];
            #pragma unroll
            for (int j = 0; j < 8; j++) {
                float4 v0 = u0[j], v1 = u1[j], v2 = u2[j];
                accA[4*j+0] = fmaf(a0A, v0.x, accA[4*j+0]);
                accA[4*j+0] = fmaf(a1A, v1.x, accA[4*j+0]);
                accA[4*j+0] = fmaf(a2A, v2.x, accA[4*j+0]);
                accA[4*j+1] = fmaf(a0A, v0.y, accA[4*j+1]);
                accA[4*j+1] = fmaf(a1A, v1.y, accA[4*j+1]);
                accA[4*j+1] = fmaf(a2A, v2.y, accA[4*j+1]);
                accA[4*j+2] = fmaf(a0A, v0.z, accA[4*j+2]);
                accA[4*j+2] = fmaf(a1A, v1.z, accA[4*j+2]);
                accA[4*j+2] = fmaf(a2A, v2.z, accA[4*j+2]);
                accA[4*j+3] = fmaf(a0A, v0.w, accA[4*j+3]);
                accA[4*j+3] = fmaf(a1A, v1.w, accA[4*j+3]);
                accA[4*j+3] = fmaf(a2A, v2.w, accA[4*j+3]);
                accB[4*j+0] = fmaf(a0B, v0.x, accB[4*j+0]);
                accB[4*j+0] = fmaf(a1B, v1.x, accB[4*j+0]);
                accB[4*j+0] = fmaf(a2B, v2.x, accB[4*j+0]);
                accB[4*j+1] = fmaf(a0B, v0.y, accB[4*j+1]);
                accB[4*j+1] = fmaf(a1B, v1.y, accB[4*j+1]);
                accB[4*j+1] = fmaf(a2B, v2.y, accB[4*j+1]);
                accB[4*j+2] = fmaf(a0B, v0.z, accB[4*j+2]);
                accB[4*j+2] = fmaf(a1B, v1.z, accB[4*j+2]);
                accB[4*j+2] = fmaf(a2B, v2.z, accB[4*j+2]);
                accB[4*j+3] = fmaf(a0B, v0.w, accB[4*j+3]);
                accB[4*j+3] = fmaf(a1B, v1.w, accB[4*j+3]);
                accB[4*j+3] = fmaf(a2B, v2.w, accB[4*j+3]);
            }
        }
        #pragma unroll
        for (int c = 0; c < H1C; c++) {
            S->h1s[c][iA] = vA ? fmaxf(__fadd_rn(accA[c], S->b1s[c]), 0.0f) : 0.0f;
            S->h1s[c][iB] = fmaxf(__fadd_rn(accB[c], S->b1s[c]), 0.0f);
        }
    }
    // leftover columns 256, 257 (threads 0 and 1)
    if (tid < 2) {
        const int i = tid + 256;
        const int tp = t0 + i - 1;
        if (tp < TT) {
            float acc1[H1C];
            #pragma unroll
            for (int c = 0; c < H1C; c++) acc1[c] = 0.0f;
            #pragma unroll 1
            for (int cin = 0; cin < CIN; cin++) {
                const float* xr = xb + cin * TT;
                float a0 = __ldg(xr + tp - 1);
                float a1 = __ldg(xr + tp);
                float a2 = (tp < TT - 1) ? __ldg(xr + tp + 1) : 0.0f;
                const float4* u0 = (const float4*)&S->w1s[cin * 96];
                const float4* u1 = (const float4*)&S->w1s[cin * 96 + 32];
                const float4* u2 = (const float4*)&S->w1s[cin * 96 + 64];
                #pragma unroll
                for (int j = 0; j < 8; j++) {
                    float4 v0 = u0[j], v1 = u1[j], v2 = u2[j];
                    #pragma unroll
                    for (int q = 0; q < 4; q++) {
                        float w0 = (&v0.x)[q], w1v = (&v1.x)[q], w2v = (&v2.x)[q];
                        acc1[4*j+q] = fmaf(a0, w0, acc1[4*j+q]);
                        acc1[4*j+q] = fmaf(a1, w1v, acc1[4*j+q]);
                        acc1[4*j+q] = fmaf(a2, w2v, acc1[4*j+q]);
                    }
                }
            }
            #pragma unroll
            for (int c = 0; c < H1C; c++)
                S->h1s[c][i] = fmaxf(__fadd_rn(acc1[c], S->b1s[c]), 0.0f);
        } else {
            #pragma unroll
            for (int c = 0; c < H1C; c++) S->h1s[c][i] = 0.0f;
        }
    }
    __syncthreads();

    // ---- conv2 (32->64, k3, pad1) + ReLU: two adjacent positions per thread,
    // shared weight loads; per-channel FMA chain keeps strict (ci, kw) order.
    const int tA = t0 + 2 * tid;       // position 0
    float acc0[H2C], acc1[H2C];
    #pragma unroll
    for (int c = 0; c < H2C; c++) { acc0[c] = 0.0f; acc1[c] = 0.0f; }
    #pragma unroll 1
    for (int ci = 0; ci < H1C; ci++) {
        // cols 2tid..2tid+3: two aligned float2 loads (conflict-free)
        float2 hA = *(const float2*)&S->h1s[ci][2 * tid];
        float2 hB = *(const float2*)&S->h1s[ci][2 * tid + 2];
        float p0a0 = hA.x, p0a1 = hA.y, p0a2 = hB.x;
        float p1a0 = hA.y, p1a1 = hB.x, p1a2 = hB.y;
        const float4* u0 = (const float4*)&S->w2s[ci * 192];
        const float4* u1 = (const float4*)&S->w2s[ci * 192 + 64];
        const float4* u2 = (const float4*)&S->w2s[ci * 192 + 128];
        #pragma unroll
        for (int j = 0; j < 16; j++) {
            float4 v0 = u0[j], v1 = u1[j], v2 = u2[j];
            #pragma unroll
            for (int q = 0; q < 4; q++) {
                float w0 = (&v0.x)[q], w1v = (&v1.x)[q], w2v = (&v2.x)[q];
                int c = 4 * j + q;
                acc0[c] = fmaf(p0a0, w0, acc0[c]);
                acc0[c] = fmaf(p0a1, w1v, acc0[c]);
                acc0[c] = fmaf(p0a2, w2v, acc0[c]);
                acc1[c] = fmaf(p1a0, w0, acc1[c]);
                acc1[c] = fmaf(p1a1, w1v, acc1[c]);
                acc1[c] = fmaf(p1a2, w2v, acc1[c]);
            }
        }
    }
    #pragma unroll
    for (int c = 0; c < H2C; c++) {
        acc0[c] = fmaxf(__fadd_rn(acc0[c], S->b2s[c]), 0.0f);
        acc1[c] = fmaxf(__fadd_rn(acc1[c], S->b2s[c]), 0.0f);
    }

    // ---- conv3 + tanh + FSQ + STE + projection for both positions ----
    float code_pair[2];
    float qv[2][3];
    #pragma unroll
    for (int p = 0; p < 2; p++) {
        const float* ac = (p == 0) ? acc0 : acc1;
        float s0 = 0.0f, s1 = 0.0f, s2 = 0.0f;
        #pragma unroll
        for (int c = 0; c < H2C; c++) {
            s0 = fmaf(ac[c], S->w3s[0 * H2C + c], s0);
            s1 = fmaf(ac[c], S->w3s[1 * H2C + c], s1);
            s2 = fmaf(ac[c], S->w3s[2 * H2C + c], s2);
        }
        float f0 = tanhf(__fadd_rn(s0, S->b3s[0]));
        float f1 = tanhf(__fadd_rn(s1, S->b3s[1]));
        float f2 = tanhf(__fadd_rn(s2, S->b3s[2]));
        int i0 = quant_idx<8>(f0);
        int i1 = quant_idx<6>(f1);
        int i2 = quant_idx<5>(f2);
        qv[p][0] = __fadd_rn(f0, __fsub_rn(lspf(i0, 8), f0));
        qv[p][1] = __fadd_rn(f1, __fsub_rn(lspf(i1, 6), f1));
        qv[p][2] = __fadd_rn(f2, __fsub_rn(lspf(i2, 5), f2));
        int code = i0 + i1 * 8 + i2 * 48;
        atomicAdd(&S->hist[code], 1);
        code_pair[p] = (float)code;
    }
    // codes: two adjacent positions -> one float2 store
    *(float2*)&out[OFF_CODES + (long)b * TT + tA] = make_float2(code_pair[0], code_pair[1]);

    // projection (3 -> 64, k=1): sequential K FMA from 0, bias epilogue
    {
        long ob = OFF_OUT + (long)b * ED * TT + tA;
        #pragma unroll
        for (int e = 0; e < ED; e++) {
            float w0 = S->wps[e * 3 + 0], w1v = S->wps[e * 3 + 1], w2v = S->wps[e * 3 + 2];
            float be = S->bps[e];
            float r0 = __fmul_rn(qv[0][0], w0);
            r0 = fmaf(qv[0][1], w1v, r0);
            r0 = fmaf(qv[0][2], w2v, r0);
            float r1 = __fmul_rn(qv[1][0], w0);
            r1 = fmaf(qv[1][1], w1v, r1);
            r1 = fmaf(qv[1][2], w2v, r1);
            *(float2*)&out[ob + (long)e * TT] =
                make_float2(__fadd_rn(r0, be), __fadd_rn(r1, be));
        }
    }

    __syncthreads();
    for (int i = tid; i < NCODE; i += 128) {
        int h = S->hist[i];
        if (h) atomicAdd(&g_counts[i], h);
    }
}

__global__ void finalize_kernel(float* __restrict__ out) {
    __shared__ float red[256];
    int tid = threadIdx.x;
    float term = 0.0f;
    if (tid < NCODE) {
        float c = (float)g_counts[tid];
        g_counts[tid] = 0;                       // reset for next graph replay
        float p = c * (1.0f / (float)((long)NB * TT));
        out[OFF_PROBS + tid] = p;
        if (p > 0.0f) term = -p * logf(p);
    }
    red[tid] = term;
    __syncthreads();
    #pragma unroll
    for (int s = 128; s > 0; s >>= 1) {
        if (tid < s) red[tid] += red[tid + s];
        __syncthreads();
    }
    if (tid == 0) out[OFF_PERP] = fmaxf(expf(red[0]), 1.0f);
}

extern "C" void kernel_launch(void* const* d_in, const int* in_sizes, int n_in,
                              void* d_out, int out_size) {
    const float* x  = (const float*)d_in[0];
    const float* w1 = (const float*)d_in[1];
    const float* b1 = (const float*)d_in[2];
    const float* w2 = (const float*)d_in[3];
    const float* b2 = (const float*)d_in[4];
    const float* w3 = (const float*)d_in[5];
    const float* b3 = (const float*)d_in[6];
    const float* wp = (const float*)d_in[7];
    const float* bp = (const float*)d_in[8];
    float* out = (float*)d_out;

    cudaFuncSetAttribute(fsq_main_kernel,
                         cudaFuncAttributeMaxDynamicSharedMemorySize,
                         (int)sizeof(Smem));

    fsq_main_kernel<<<NB * (TT / TILE), 128, sizeof(Smem)>>>(
        x, w1, b1, w2, b2, w3, b3, wp, bp, out);
    finalize_kernel<<<1, 256>>>(out);
}